// round 11
// baseline (speedup 1.0000x reference)
#include <cuda_runtime.h>
#include <cuda_fp16.h>
#include <cstdint>

#define N_NODES 50000
#define N_EDGES 1600000
#define D 512

// ---------------- device scratch ----------------
__device__ __half g_hidden_h[(long long)N_NODES * D];  // fp16 hidden
__device__ __half g_xh[(long long)N_NODES * D];        // fp16 x
__device__ __half g_wTh[D * D];                        // fp16 w^T [n][k]
__device__ int   g_rowstart[N_NODES + 1];
__device__ int   g_cursor[N_NODES];
__device__ int   g_blocksum[64];
__device__ int2  g_epack[N_EDGES];
__device__ int   g_idx_is64;

// ---------------- dtype probe + zero counts ----------------
__global__ void probe_zero(const int* __restrict__ er32, const int* __restrict__ ec32) {
    int i = blockIdx.x * blockDim.x + threadIdx.x;
    if (i < N_NODES) g_cursor[i] = 0;
    if (i == 0) {
        int looks64 = 1;
        for (int j = 0; j < 256; j++) {
            if (er32[2 * j + 1] != 0) { looks64 = 0; break; }
            if (ec32[2 * j + 1] != 0) { looks64 = 0; break; }
        }
        g_idx_is64 = looks64;
    }
}

__device__ __forceinline__ int load_idx(const void* p, int e, int is64) {
    long long v;
    if (is64) v = ((const long long*)p)[e];
    else      v = ((const int*)p)[e];
    if (v < 0) v = 0;
    if (v >= N_NODES) v = N_NODES - 1;
    return (int)v;
}

// ---------------- fp16 converts ----------------
__global__ void conv_w(const float* __restrict__ w) {
    int idx = blockIdx.x * blockDim.x + threadIdx.x;
    if (idx >= D * D) return;
    int k = idx >> 9, n = idx & 511;
    g_wTh[n * D + k] = __float2half_rn(w[idx]);   // w[k][n] -> wT[n][k]
}

__global__ void conv_x(const float* __restrict__ x) {
    long long i = (long long)(blockIdx.x * blockDim.x + threadIdx.x) * 4;
    if (i >= (long long)N_NODES * D) return;
    float4 v = *(const float4*)(x + i);
    __half2* ph = (__half2*)(g_xh + i);
    ph[0] = __floats2half2_rn(v.x, v.y);
    ph[1] = __floats2half2_rn(v.z, v.w);
}

// ---------------- tensor-core GEMM (fp16 mma.sync, BK=64, 3 stages) ------
#define BK 64
#define ROWPAD 72                 // halves per smem row (144B, conflict-free)
#define SA (128 * ROWPAD)         // halves per matrix per stage
#define NSTAGE 3

__device__ __forceinline__ void cpa16(uint32_t dst, const void* src) {
    asm volatile("cp.async.cg.shared.global [%0], [%1], 16;\n" :: "r"(dst), "l"(src));
}
__device__ __forceinline__ void cpa_commit() { asm volatile("cp.async.commit_group;\n"); }
template <int N>
__device__ __forceinline__ void cpa_wait() { asm volatile("cp.async.wait_group %0;\n" :: "n"(N)); }

__device__ __forceinline__ void ldsm_x4(uint32_t* r, uint32_t addr) {
    asm volatile("ldmatrix.sync.aligned.m8n8.x4.shared.b16 {%0,%1,%2,%3}, [%4];\n"
                 : "=r"(r[0]), "=r"(r[1]), "=r"(r[2]), "=r"(r[3]) : "r"(addr));
}
__device__ __forceinline__ void ldsm_x2(uint32_t* r, uint32_t addr) {
    asm volatile("ldmatrix.sync.aligned.m8n8.x2.shared.b16 {%0,%1}, [%2];\n"
                 : "=r"(r[0]), "=r"(r[1]) : "r"(addr));
}
__device__ __forceinline__ void mma16816(float* c, const uint32_t* a, const uint32_t* b) {
    asm volatile("mma.sync.aligned.m16n8k16.row.col.f32.f16.f16.f32 "
                 "{%0,%1,%2,%3}, {%4,%5,%6,%7}, {%8,%9}, {%0,%1,%2,%3};\n"
                 : "+f"(c[0]), "+f"(c[1]), "+f"(c[2]), "+f"(c[3])
                 : "r"(a[0]), "r"(a[1]), "r"(a[2]), "r"(a[3]), "r"(b[0]), "r"(b[1]));
}

__global__ __launch_bounds__(256, 2) void gemm_fp16(int ncol_off) {
    extern __shared__ __half smem[];
    __half* sA = smem;                    // NSTAGE stages
    __half* sB = smem + NSTAGE * SA;      // NSTAGE stages

    const int tid  = threadIdx.x;
    const int lane = tid & 31;
    const int wid  = tid >> 5;
    const int warp_m = wid & 1;
    const int warp_n = wid >> 1;
    const int brow = blockIdx.y * 128;
    const int bcol = blockIdx.x * 128 + ncol_off;

    const int lrow  = tid >> 1;                 // 0..127
    const int c16b  = (tid & 1) * 4;            // chunk base 0 or 4

    int arow = brow + lrow; if (arow >= N_NODES) arow = N_NODES - 1;
    const int bn = bcol + lrow;

    const __half* srcA = g_xh  + (long long)arow * D;
    const __half* srcB = g_wTh + bn * D;

    const int dstoff = lrow * ROWPAD + c16b * 8;   // halves

    float acc[4][4][4];
    #pragma unroll
    for (int i = 0; i < 4; i++)
        #pragma unroll
        for (int j = 0; j < 4; j++)
            #pragma unroll
            for (int c = 0; c < 4; c++) acc[i][j][c] = 0.f;

    const int NK = D / BK;   // 8

    auto issue_stage = [&](int kt, int st) {
        int k0 = kt * BK + c16b * 8;
        uint32_t dA = (uint32_t)__cvta_generic_to_shared(sA + st * SA + dstoff);
        uint32_t dB = (uint32_t)__cvta_generic_to_shared(sB + st * SA + dstoff);
        #pragma unroll
        for (int i = 0; i < 4; i++) {
            cpa16(dA + i * 16, srcA + k0 + i * 8);
            cpa16(dB + i * 16, srcB + k0 + i * 8);
        }
        cpa_commit();
    };

    issue_stage(0, 0);
    issue_stage(1, 1);

    for (int kt = 0; kt < NK; kt++) {
        int st = kt % NSTAGE;
        if (kt + 2 < NK) { issue_stage(kt + 2, (kt + 2) % NSTAGE); cpa_wait<2>(); }
        else if (kt + 1 < NK) { cpa_wait<1>(); }
        else { cpa_wait<0>(); }
        __syncthreads();

        #pragma unroll
        for (int kk = 0; kk < 4; kk++) {   // four k16 slices in BK=64
            uint32_t af[4][4];
            uint32_t bf[4][2];

            const int arow_t = warp_m * 64 + (lane & 15);
            const int akoff  = kk * 16 + (lane >> 4) * 8;
            #pragma unroll
            for (int mt = 0; mt < 4; mt++) {
                int off = st * SA + (arow_t + mt * 16) * ROWPAD + akoff;
                ldsm_x4(af[mt], (uint32_t)__cvta_generic_to_shared(sA + off));
            }
            const int brow_t = warp_n * 32 + (lane & 7);
            const int bkoff  = kk * 16 + ((lane >> 3) & 1) * 8;
            #pragma unroll
            for (int nt = 0; nt < 4; nt++) {
                int off = st * SA + (brow_t + nt * 8) * ROWPAD + bkoff;
                ldsm_x2(bf[nt], (uint32_t)__cvta_generic_to_shared(sB + off));
            }

            #pragma unroll
            for (int mt = 0; mt < 4; mt++)
                #pragma unroll
                for (int nt = 0; nt < 4; nt++)
                    mma16816(acc[mt][nt], af[mt], bf[nt]);
        }
        __syncthreads();
    }

    #pragma unroll
    for (int mt = 0; mt < 4; mt++) {
        int row0 = brow + warp_m * 64 + mt * 16 + (lane >> 2);
        #pragma unroll
        for (int nt = 0; nt < 4; nt++) {
            int col = bcol + warp_n * 32 + nt * 8 + (lane & 3) * 2;
            if (row0 < N_NODES)
                *(__half2*)(g_hidden_h + (long long)row0 * D + col) =
                    __floats2half2_rn(acc[mt][nt][0], acc[mt][nt][1]);
            if (row0 + 8 < N_NODES)
                *(__half2*)(g_hidden_h + (long long)(row0 + 8) * D + col) =
                    __floats2half2_rn(acc[mt][nt][2], acc[mt][nt][3]);
        }
    }
}

// ---------------- CSR build ----------------
__global__ void hist_rows(const void* __restrict__ er) {
    int e = blockIdx.x * blockDim.x + threadIdx.x;
    if (e < N_EDGES) atomicAdd(&g_cursor[load_idx(er, e, g_idx_is64)], 1);
}

#define SCAN_BLOCKS ((N_NODES + 1023) / 1024)

__global__ __launch_bounds__(1024) void scan_local() {
    __shared__ int sdata[1024];
    int b = blockIdx.x, t = threadIdx.x;
    int i = b * 1024 + t;
    int v = (i < N_NODES) ? g_cursor[i] : 0;
    sdata[t] = v;
    __syncthreads();
    for (int off = 1; off < 1024; off <<= 1) {
        int tv = (t >= off) ? sdata[t - off] : 0;
        __syncthreads();
        sdata[t] += tv;
        __syncthreads();
    }
    if (i < N_NODES) g_rowstart[i] = sdata[t] - v;
    if (t == 1023) g_blocksum[b] = sdata[1023];
}

__global__ void scan_offsets() {
    if (threadIdx.x == 0) {
        int run = 0;
        for (int j = 0; j < SCAN_BLOCKS; j++) {
            int s = g_blocksum[j];
            g_blocksum[j] = run;
            run += s;
        }
        g_rowstart[N_NODES] = run;
    }
}

__global__ __launch_bounds__(1024) void scan_add() {
    int i = blockIdx.x * 1024 + threadIdx.x;
    if (i < N_NODES) {
        int v = g_rowstart[i] + g_blocksum[blockIdx.x];
        g_rowstart[i] = v;
        g_cursor[i]   = v;
    }
}

__global__ void bucket_edges(const float* __restrict__ ev,
                             const void* __restrict__ er,
                             const void* __restrict__ ec) {
    int e = blockIdx.x * blockDim.x + threadIdx.x;
    if (e < N_EDGES) {
        int is64 = g_idx_is64;
        int row = load_idx(er, e, is64);
        int col = load_idx(ec, e, is64);
        int pos = atomicAdd(&g_cursor[row], 1);
        if (pos >= 0 && pos < N_EDGES)
            g_epack[pos] = make_int2(col, __float_as_int(ev[e]));
    }
}

// ---------------- gather SpMM over a 256-col part -------------------------
// 4 subgroups x 32 lanes; each lane owns one 16B slice (8 halves).
// part=0: cols [0,256), part=1: cols [256,512).
__global__ __launch_bounds__(128) void gather_part(const float* __restrict__ bias,
                                                   float* __restrict__ out,
                                                   int part) {
    const int node  = blockIdx.x;
    const int start = g_rowstart[node];
    const int end   = g_rowstart[node + 1];

    __shared__ int2  s_e[256];
    __shared__ float s_part[3][32][8];

    const int tid = threadIdx.x;
    const int sub = tid >> 5;            // 0..3
    const int l   = tid & 31;
    const int slice = part * 32 + l;     // uint4 index within row (64 total)

    const uint4* __restrict__ H4 = (const uint4*)g_hidden_h;

    float acc[8];
    #pragma unroll
    for (int k = 0; k < 8; k++) acc[k] = 0.f;

    for (int base = start; base < end; base += 256) {
        int cnt = min(end - base, 256);
        for (int i = tid; i < cnt; i += 128)
            s_e[i] = g_epack[base + i];
        __syncthreads();
        #pragma unroll 2
        for (int i = sub; i < cnt; i += 4) {
            int2 p = s_e[i];
            float v = __int_as_float(p.y);
            uint4 h = H4[(long long)p.x * (D / 8) + slice];
            float2 f0 = __half22float2(*(const __half2*)&h.x);
            float2 f1 = __half22float2(*(const __half2*)&h.y);
            float2 f2 = __half22float2(*(const __half2*)&h.z);
            float2 f3 = __half22float2(*(const __half2*)&h.w);
            acc[0] += v * f0.x; acc[1] += v * f0.y;
            acc[2] += v * f1.x; acc[3] += v * f1.y;
            acc[4] += v * f2.x; acc[5] += v * f2.y;
            acc[6] += v * f3.x; acc[7] += v * f3.y;
        }
        __syncthreads();
    }

    if (sub != 0) {
        #pragma unroll
        for (int k = 0; k < 8; k++) s_part[sub - 1][l][k] = acc[k];
    }
    __syncthreads();
    if (sub == 0) {
        #pragma unroll
        for (int k = 0; k < 8; k++)
            acc[k] += s_part[0][l][k] + s_part[1][l][k] + s_part[2][l][k];
        const float4* b4 = (const float4*)bias;
        float4 bv0 = b4[part * 64 + l * 2];
        float4 bv1 = b4[part * 64 + l * 2 + 1];
        float4 o0 = make_float4(acc[0] + bv0.x, acc[1] + bv0.y,
                                acc[2] + bv0.z, acc[3] + bv0.w);
        float4 o1 = make_float4(acc[4] + bv1.x, acc[5] + bv1.y,
                                acc[6] + bv1.z, acc[7] + bv1.w);
        float4* dst = (float4*)(out + (long long)node * D + part * 256 + l * 8);
        dst[0] = o0;
        dst[1] = o1;
    }
}

// ---------------- launcher: fork/join + column-part pipelining -----------
extern "C" void kernel_launch(void* const* d_in, const int* in_sizes, int n_in,
                              void* d_out, int out_size) {
    const float* x    = (const float*)d_in[0];
    const float* w    = (const float*)d_in[1];
    const float* bias = (const float*)d_in[2];
    const float* ev   = (const float*)d_in[3];
    const void*  er   = d_in[4];
    const void*  ec   = d_in[5];
    float* out = (float*)d_out;

    static const int GEMM_SMEM = 2 * NSTAGE * SA * (int)sizeof(__half); // 110592

    static cudaStream_t s_side = nullptr;
    static cudaEvent_t  ev_fork = nullptr, ev_g1 = nullptr, ev_g2 = nullptr;
    if (s_side == nullptr) {
        cudaStreamCreateWithFlags(&s_side, cudaStreamNonBlocking);
        cudaEventCreateWithFlags(&ev_fork, cudaEventDisableTiming);
        cudaEventCreateWithFlags(&ev_g1, cudaEventDisableTiming);
        cudaEventCreateWithFlags(&ev_g2, cudaEventDisableTiming);
        cudaFuncSetAttribute(gemm_fp16,
                             cudaFuncAttributeMaxDynamicSharedMemorySize, GEMM_SMEM);
    }

    // fork side stream off the capture-origin stream
    cudaEventRecord(ev_fork, 0);
    cudaStreamWaitEvent(s_side, ev_fork, 0);

    // ---- side chain: converts + GEMM in two 256-col passes ----
    conv_w<<<(D * D + 255) / 256, 256, 0, s_side>>>(w);
    conv_x<<<(N_NODES * D / 4 + 255) / 256, 256, 0, s_side>>>(x);
    dim3 hgrid(2, (N_NODES + 127) / 128);
    gemm_fp16<<<hgrid, 256, GEMM_SMEM, s_side>>>(0);
    cudaEventRecord(ev_g1, s_side);
    gemm_fp16<<<hgrid, 256, GEMM_SMEM, s_side>>>(256);
    cudaEventRecord(ev_g2, s_side);

    // ---- main chain: CSR build ----
    probe_zero<<<(N_NODES + 255) / 256, 256>>>((const int*)er, (const int*)ec);
    hist_rows<<<(N_EDGES + 255) / 256, 256>>>(er);
    scan_local<<<SCAN_BLOCKS, 1024>>>();
    scan_offsets<<<1, 32>>>();
    scan_add<<<SCAN_BLOCKS, 1024>>>();
    bucket_edges<<<(N_EDGES + 255) / 256, 256>>>(ev, er, ec);

    // gather part 0 overlaps GEMM pass 2
    cudaStreamWaitEvent(0, ev_g1, 0);
    gather_part<<<N_NODES, 128>>>(bias, out, 0);
    cudaStreamWaitEvent(0, ev_g2, 0);
    gather_part<<<N_NODES, 128>>>(bias, out, 1);
}

// round 12
// speedup vs baseline: 1.1672x; 1.1672x over previous
#include <cuda_runtime.h>
#include <cuda_fp16.h>
#include <cstdint>

#define N_NODES 50000
#define N_EDGES 1600000
#define D 512

// ---------------- device scratch ----------------
__device__ __half g_hidden_h[(long long)N_NODES * D];  // fp16 hidden
__device__ __half g_xh[(long long)N_NODES * D];        // fp16 x
__device__ __half g_wTh[D * D];                        // fp16 w^T [n][k]
__device__ int   g_rowstart[N_NODES + 1];
__device__ int   g_cursor[N_NODES];
__device__ int   g_blocksum[64];
__device__ int2  g_epack[N_EDGES];
__device__ int   g_idx_is64;

// ---------------- dtype probe + zero counts ----------------
__global__ void probe_zero(const int* __restrict__ er32, const int* __restrict__ ec32) {
    int i = blockIdx.x * blockDim.x + threadIdx.x;
    if (i < N_NODES) g_cursor[i] = 0;
    if (i == 0) {
        int looks64 = 1;
        for (int j = 0; j < 256; j++) {
            if (er32[2 * j + 1] != 0) { looks64 = 0; break; }
            if (ec32[2 * j + 1] != 0) { looks64 = 0; break; }
        }
        g_idx_is64 = looks64;
    }
}

__device__ __forceinline__ int load_idx(const void* p, int e, int is64) {
    long long v;
    if (is64) v = ((const long long*)p)[e];
    else      v = ((const int*)p)[e];
    if (v < 0) v = 0;
    if (v >= N_NODES) v = N_NODES - 1;
    return (int)v;
}

// ---------------- fused fp16 converts (x + w in one launch) --------------
#define CONVX_BLOCKS ((N_NODES * D / 4 + 255) / 256)

__global__ void conv_xw(const float* __restrict__ x, const float* __restrict__ w) {
    long long i = (long long)(blockIdx.x * blockDim.x + threadIdx.x) * 4;
    if (i < (long long)N_NODES * D) {
        float4 v = *(const float4*)(x + i);
        __half2* ph = (__half2*)(g_xh + i);
        ph[0] = __floats2half2_rn(v.x, v.y);
        ph[1] = __floats2half2_rn(v.z, v.w);
    }
    // first 1024 blocks also convert+transpose w (256 elems each)
    if (blockIdx.x < (D * D) / 256) {
        int idx = blockIdx.x * 256 + threadIdx.x;
        int k = idx >> 9, n = idx & 511;
        g_wTh[n * D + k] = __float2half_rn(w[idx]);   // w[k][n] -> wT[n][k]
    }
}

// ---------------- tensor-core GEMM (fp16 mma.sync, BK=64, 3 stages, 1 bar)
#define BK 64
#define ROWPAD 72                 // halves per smem row (144B, conflict-free)
#define SA (128 * ROWPAD)         // halves per matrix per stage
#define NSTAGE 3

__device__ __forceinline__ void cpa16(uint32_t dst, const void* src) {
    asm volatile("cp.async.cg.shared.global [%0], [%1], 16;\n" :: "r"(dst), "l"(src));
}
__device__ __forceinline__ void cpa_commit() { asm volatile("cp.async.commit_group;\n"); }
template <int N>
__device__ __forceinline__ void cpa_wait() { asm volatile("cp.async.wait_group %0;\n" :: "n"(N)); }

__device__ __forceinline__ void ldsm_x4(uint32_t* r, uint32_t addr) {
    asm volatile("ldmatrix.sync.aligned.m8n8.x4.shared.b16 {%0,%1,%2,%3}, [%4];\n"
                 : "=r"(r[0]), "=r"(r[1]), "=r"(r[2]), "=r"(r[3]) : "r"(addr));
}
__device__ __forceinline__ void mma16816(float* c, const uint32_t* a, const uint32_t* b) {
    asm volatile("mma.sync.aligned.m16n8k16.row.col.f32.f16.f16.f32 "
                 "{%0,%1,%2,%3}, {%4,%5,%6,%7}, {%8,%9}, {%0,%1,%2,%3};\n"
                 : "+f"(c[0]), "+f"(c[1]), "+f"(c[2]), "+f"(c[3])
                 : "r"(a[0]), "r"(a[1]), "r"(a[2]), "r"(a[3]), "r"(b[0]), "r"(b[1]));
}

__global__ __launch_bounds__(256, 2) void gemm_fp16() {
    extern __shared__ __half smem[];
    __half* sA = smem;                    // NSTAGE stages
    __half* sB = smem + NSTAGE * SA;      // NSTAGE stages

    const int tid  = threadIdx.x;
    const int lane = tid & 31;
    const int wid  = tid >> 5;
    const int warp_m = wid & 1;
    const int warp_n = wid >> 1;
    const int brow = blockIdx.y * 128;
    const int bcol = blockIdx.x * 128;

    const int lrow  = tid >> 1;                 // 0..127
    const int c16b  = (tid & 1) * 4;            // chunk base 0 or 4

    int arow = brow + lrow; if (arow >= N_NODES) arow = N_NODES - 1;
    const int bn = bcol + lrow;

    const __half* srcA = g_xh  + (long long)arow * D;
    const __half* srcB = g_wTh + bn * D;

    const int dstoff = lrow * ROWPAD + c16b * 8;   // halves

    float acc[4][4][4];
    #pragma unroll
    for (int i = 0; i < 4; i++)
        #pragma unroll
        for (int j = 0; j < 4; j++)
            #pragma unroll
            for (int c = 0; c < 4; c++) acc[i][j][c] = 0.f;

    const int NK = D / BK;   // 8

    auto issue_stage = [&](int kt, int st) {
        int k0 = kt * BK + c16b * 8;
        uint32_t dA = (uint32_t)__cvta_generic_to_shared(sA + st * SA + dstoff);
        uint32_t dB = (uint32_t)__cvta_generic_to_shared(sB + st * SA + dstoff);
        #pragma unroll
        for (int i = 0; i < 4; i++) {
            cpa16(dA + i * 16, srcA + k0 + i * 8);
            cpa16(dB + i * 16, srcB + k0 + i * 8);
        }
        cpa_commit();
    };

    issue_stage(0, 0);
    issue_stage(1, 1);

    // A-fragment ldmatrix address pieces (per warp)
    const int arow_t = warp_m * 64 + (lane & 15);
    const int asel   = (lane >> 4) * 8;
    // B-fragment x4 address: covers two n-tiles (16 rows) per instruction
    const int brow4  = warp_n * 32 + ((lane >> 4) << 3) + (lane & 7);
    const int bsel   = ((lane >> 3) & 1) * 8;

    for (int kt = 0; kt < NK; kt++) {
        const int st = kt % NSTAGE;
        if (kt + 2 < NK) cpa_wait<1>();     // stage st ready; next may be in flight
        else             cpa_wait<0>();
        __syncthreads();                    // all warps done with compute kt-1
        if (kt + 2 < NK) issue_stage(kt + 2, (kt + 2) % NSTAGE);

        #pragma unroll
        for (int kk = 0; kk < 4; kk++) {   // four k16 slices in BK=64
            uint32_t af[4][4];
            uint32_t bf[4][2];

            const int akoff = kk * 16 + asel;
            #pragma unroll
            for (int mt = 0; mt < 4; mt++) {
                int off = st * SA + (arow_t + mt * 16) * ROWPAD + akoff;
                ldsm_x4(af[mt], (uint32_t)__cvta_generic_to_shared(sA + off));
            }
            const int bkoff = kk * 16 + bsel;
            #pragma unroll
            for (int np = 0; np < 2; np++) {   // pairs (nt=2*np, 2*np+1)
                int off = st * SA + (brow4 + np * 16) * ROWPAD + bkoff;
                uint32_t r[4];
                ldsm_x4(r, (uint32_t)__cvta_generic_to_shared(sB + off));
                bf[2 * np][0] = r[0]; bf[2 * np][1] = r[1];
                bf[2 * np + 1][0] = r[2]; bf[2 * np + 1][1] = r[3];
            }

            #pragma unroll
            for (int mt = 0; mt < 4; mt++)
                #pragma unroll
                for (int nt = 0; nt < 4; nt++)
                    mma16816(acc[mt][nt], af[mt], bf[nt]);
        }
    }
    __syncthreads();

    #pragma unroll
    for (int mt = 0; mt < 4; mt++) {
        int row0 = brow + warp_m * 64 + mt * 16 + (lane >> 2);
        #pragma unroll
        for (int nt = 0; nt < 4; nt++) {
            int col = bcol + warp_n * 32 + nt * 8 + (lane & 3) * 2;
            if (row0 < N_NODES)
                *(__half2*)(g_hidden_h + (long long)row0 * D + col) =
                    __floats2half2_rn(acc[mt][nt][0], acc[mt][nt][1]);
            if (row0 + 8 < N_NODES)
                *(__half2*)(g_hidden_h + (long long)(row0 + 8) * D + col) =
                    __floats2half2_rn(acc[mt][nt][2], acc[mt][nt][3]);
        }
    }
}

// ---------------- CSR build ----------------
__global__ void hist_rows(const void* __restrict__ er) {
    int e = blockIdx.x * blockDim.x + threadIdx.x;
    if (e < N_EDGES) atomicAdd(&g_cursor[load_idx(er, e, g_idx_is64)], 1);
}

#define SCAN_BLOCKS ((N_NODES + 1023) / 1024)

__global__ __launch_bounds__(1024) void scan_local() {
    __shared__ int sdata[1024];
    int b = blockIdx.x, t = threadIdx.x;
    int i = b * 1024 + t;
    int v = (i < N_NODES) ? g_cursor[i] : 0;
    sdata[t] = v;
    __syncthreads();
    for (int off = 1; off < 1024; off <<= 1) {
        int tv = (t >= off) ? sdata[t - off] : 0;
        __syncthreads();
        sdata[t] += tv;
        __syncthreads();
    }
    if (i < N_NODES) g_rowstart[i] = sdata[t] - v;
    if (t == 1023) g_blocksum[b] = sdata[1023];
}

__global__ void scan_offsets() {
    if (threadIdx.x == 0) {
        int run = 0;
        for (int j = 0; j < SCAN_BLOCKS; j++) {
            int s = g_blocksum[j];
            g_blocksum[j] = run;
            run += s;
        }
        g_rowstart[N_NODES] = run;
    }
}

__global__ __launch_bounds__(1024) void scan_add() {
    int i = blockIdx.x * 1024 + threadIdx.x;
    if (i < N_NODES) {
        int v = g_rowstart[i] + g_blocksum[blockIdx.x];
        g_rowstart[i] = v;
        g_cursor[i]   = v;
    }
}

__global__ void bucket_edges(const float* __restrict__ ev,
                             const void* __restrict__ er,
                             const void* __restrict__ ec) {
    int e = blockIdx.x * blockDim.x + threadIdx.x;
    if (e < N_EDGES) {
        int is64 = g_idx_is64;
        int row = load_idx(er, e, is64);
        int col = load_idx(ec, e, is64);
        int pos = atomicAdd(&g_cursor[row], 1);
        if (pos >= 0 && pos < N_EDGES)
            g_epack[pos] = make_int2(col, __float_as_int(ev[e]));
    }
}

// ---------------- gather SpMM: 2 x 64-lane subgroups, LDG.128 per edge ---
__global__ __launch_bounds__(128) void gather_spmm(const float* __restrict__ bias,
                                                   float* __restrict__ out) {
    const int node  = blockIdx.x;
    const int start = g_rowstart[node];
    const int end   = g_rowstart[node + 1];

    __shared__ int2  s_e[256];
    __shared__ float s_part[64 * 8];     // subgroup-1 partials

    const int tid = threadIdx.x;
    const int sub = tid >> 6;            // 0 or 1
    const int l   = tid & 63;            // 16B slice: cols [l*8, l*8+8)

    const uint4* __restrict__ H4 = (const uint4*)g_hidden_h;   // 8 halves per uint4

    float acc[8];
    #pragma unroll
    for (int k = 0; k < 8; k++) acc[k] = 0.f;

    for (int base = start; base < end; base += 256) {
        int cnt = min(end - base, 256);
        for (int i = tid; i < cnt; i += 128)
            s_e[i] = g_epack[base + i];
        __syncthreads();
        #pragma unroll 4
        for (int i = sub; i < cnt; i += 2) {
            int2 p = s_e[i];
            float v = __int_as_float(p.y);
            uint4 h = H4[(long long)p.x * (D / 8) + l];
            float2 f0 = __half22float2(*(const __half2*)&h.x);
            float2 f1 = __half22float2(*(const __half2*)&h.y);
            float2 f2 = __half22float2(*(const __half2*)&h.z);
            float2 f3 = __half22float2(*(const __half2*)&h.w);
            acc[0] += v * f0.x; acc[1] += v * f0.y;
            acc[2] += v * f1.x; acc[3] += v * f1.y;
            acc[4] += v * f2.x; acc[5] += v * f2.y;
            acc[6] += v * f3.x; acc[7] += v * f3.y;
        }
        __syncthreads();
    }

    if (sub == 1) {
        #pragma unroll
        for (int k = 0; k < 8; k++) s_part[l * 8 + k] = acc[k];
    }
    __syncthreads();
    if (sub == 0) {
        const float4* b4 = (const float4*)bias;
        float4 o0, o1;
        o0.x = acc[0] + s_part[l * 8 + 0];
        o0.y = acc[1] + s_part[l * 8 + 1];
        o0.z = acc[2] + s_part[l * 8 + 2];
        o0.w = acc[3] + s_part[l * 8 + 3];
        o1.x = acc[4] + s_part[l * 8 + 4];
        o1.y = acc[5] + s_part[l * 8 + 5];
        o1.z = acc[6] + s_part[l * 8 + 6];
        o1.w = acc[7] + s_part[l * 8 + 7];
        float4 bv0 = b4[l * 2];
        float4 bv1 = b4[l * 2 + 1];
        o0.x += bv0.x; o0.y += bv0.y; o0.z += bv0.z; o0.w += bv0.w;
        o1.x += bv1.x; o1.y += bv1.y; o1.z += bv1.z; o1.w += bv1.w;
        float4* dst = (float4*)(out + (long long)node * D + l * 8);
        dst[0] = o0;
        dst[1] = o1;
    }
}

// ---------------- launcher: fork/join (R10 structure) --------------------
extern "C" void kernel_launch(void* const* d_in, const int* in_sizes, int n_in,
                              void* d_out, int out_size) {
    const float* x    = (const float*)d_in[0];
    const float* w    = (const float*)d_in[1];
    const float* bias = (const float*)d_in[2];
    const float* ev   = (const float*)d_in[3];
    const void*  er   = d_in[4];
    const void*  ec   = d_in[5];
    float* out = (float*)d_out;

    static const int GEMM_SMEM = 2 * NSTAGE * SA * (int)sizeof(__half); // 110592

    static cudaStream_t s_side = nullptr;
    static cudaEvent_t  ev_fork = nullptr, ev_join = nullptr;
    if (s_side == nullptr) {
        cudaStreamCreateWithFlags(&s_side, cudaStreamNonBlocking);
        cudaEventCreateWithFlags(&ev_fork, cudaEventDisableTiming);
        cudaEventCreateWithFlags(&ev_join, cudaEventDisableTiming);
        cudaFuncSetAttribute(gemm_fp16,
                             cudaFuncAttributeMaxDynamicSharedMemorySize, GEMM_SMEM);
    }

    // fork side stream off the capture-origin stream
    cudaEventRecord(ev_fork, 0);
    cudaStreamWaitEvent(s_side, ev_fork, 0);

    // ---- side chain: fused converts + full GEMM ----
    conv_xw<<<CONVX_BLOCKS, 256, 0, s_side>>>(x, w);
    dim3 ggrid(D / 128, (N_NODES + 127) / 128);
    gemm_fp16<<<ggrid, 256, GEMM_SMEM, s_side>>>();
    cudaEventRecord(ev_join, s_side);

    // ---- main chain: CSR build ----
    probe_zero<<<(N_NODES + 255) / 256, 256>>>((const int*)er, (const int*)ec);
    hist_rows<<<(N_EDGES + 255) / 256, 256>>>(er);
    scan_local<<<SCAN_BLOCKS, 1024>>>();
    scan_offsets<<<1, 32>>>();
    scan_add<<<SCAN_BLOCKS, 1024>>>();
    bucket_edges<<<(N_EDGES + 255) / 256, 256>>>(ev, er, ec);

    // join, then gather
    cudaStreamWaitEvent(0, ev_join, 0);
    gather_spmm<<<N_NODES, 128>>>(bias, out);
}